// round 5
// baseline (speedup 1.0000x reference)
#include <cuda_runtime.h>
#include <math.h>

#define BB 8
#define TT 64
#define NN 256
#define HH 256
#define DI 6
#define DO 9
#define G3 768

typedef unsigned long long u64;

__device__ __align__(16) float g_gx[(size_t)BB*TT*NN*G3];
__device__ __align__(16) float g_hseq[(size_t)BB*TT*NN*HH];
__device__ __align__(16) float g_Axseq[(size_t)BB*TT*NN*HH];
__device__ __align__(16) float g_h [BB*NN*HH];
__device__ __align__(16) float g_Ah[BB*NN*HH];
__device__ __align__(16) float g_Au[BB*NN*HH];
__device__ __align__(16) float g_z [BB*NN*HH];
__device__ int   g_cnt[NN];
__device__ int   g_col[NN*NN];
__device__ float g_val[NN*NN];

union F4U { float4 f; u64 u[2]; };

__device__ __forceinline__ void ffma2(u64& d, u64 a, u64 b){
    asm("fma.rn.f32x2 %0, %1, %2, %0;" : "+l"(d) : "l"(a), "l"(b));
}
__device__ __forceinline__ float2 unpack2(u64 v){
    float2 f; asm("mov.b64 {%0, %1}, %2;" : "=f"(f.x), "=f"(f.y) : "l"(v)); return f;
}
__device__ __forceinline__ float sigmoidf_(float x){ return 1.0f / (1.0f + __expf(-x)); }

__global__ void build_csr(const float* __restrict__ adj){
    int n = threadIdx.x;
    int c = 0;
    for (int m = 0; m < NN; m++){
        float v = adj[n*NN + m];
        if (v != 0.0f){ g_col[n*NN + c] = m; g_val[n*NN + c] = v; c++; }
    }
    g_cnt[n] = c;
}

__global__ void zero_hAh(){
    int i = blockIdx.x*256 + threadIdx.x;
    float4 z = make_float4(0,0,0,0);
    ((float4*)g_h)[i] = z;
    ((float4*)g_Ah)[i] = z;
}

// gx0 = (A (x) (x*mask)) @ Wx0 + b0, per (b,t)
__global__ void prep_gx0(const float* __restrict__ x2d, const float* __restrict__ mask,
                         const float* __restrict__ Wx0, const float* __restrict__ b0){
    __shared__ float xm[NN*DI];
    __shared__ float ax[NN*DI];
    __shared__ float Ws[DI*G3];
    __shared__ float b0s[G3];
    int bt = blockIdx.x;
    int tid = threadIdx.x;
    for (int i = tid; i < NN*DI; i += 256){
        int n = i / DI;
        xm[i] = x2d[(size_t)bt*NN*DI + i] * mask[(size_t)bt*NN + n];
    }
    for (int i = tid; i < DI*G3; i += 256) Ws[i] = Wx0[i];
    for (int i = tid; i < G3; i += 256) b0s[i] = b0[i];
    __syncthreads();
    {
        int n = tid;
        float a0=0,a1=0,a2=0,a3=0,a4=0,a5=0;
        int cn = g_cnt[n];
        for (int e = 0; e < cn; e++){
            int m = g_col[n*NN + e]; float w = g_val[n*NN + e];
            const float* xr = xm + m*DI;
            a0+=w*xr[0]; a1+=w*xr[1]; a2+=w*xr[2]; a3+=w*xr[3]; a4+=w*xr[4]; a5+=w*xr[5];
        }
        float* ar = ax + n*DI;
        ar[0]=a0; ar[1]=a1; ar[2]=a2; ar[3]=a3; ar[4]=a4; ar[5]=a5;
    }
    __syncthreads();
    float* gout = g_gx + (size_t)bt*NN*G3;
    for (int n = 0; n < NN; n++){
        const float* axr = ax + n*DI;
        float a0=axr[0],a1=axr[1],a2=axr[2],a3=axr[3],a4=axr[4],a5=axr[5];
        #pragma unroll
        for (int jj = 0; jj < 3; jj++){
            int j = tid + (jj<<8);
            gout[n*G3 + j] = b0s[j] + a0*Ws[j] + a1*Ws[G3+j] + a2*Ws[2*G3+j]
                           + a3*Ws[3*G3+j] + a4*Ws[4*G3+j] + a5*Ws[5*G3+j];
        }
    }
}

// spconv over smem tile (pitch 20), 16 cols, optional dual output
__device__ __forceinline__ void spconv16(const float* su, float* dst1, float* dst2){
    int n = threadIdx.x;
    float4 a0 = make_float4(0,0,0,0), a1 = a0, a2 = a0, a3 = a0;
    int cn = g_cnt[n];
    const int*   cp = g_col + n*NN;
    const float* vp = g_val + n*NN;
    for (int e = 0; e < cn; e++){
        int m = cp[e]; float w = vp[e];
        const float4* sm = (const float4*)(su + m*20);
        float4 s0=sm[0], s1=sm[1], s2=sm[2], s3=sm[3];
        a0.x+=w*s0.x; a0.y+=w*s0.y; a0.z+=w*s0.z; a0.w+=w*s0.w;
        a1.x+=w*s1.x; a1.y+=w*s1.y; a1.z+=w*s1.z; a1.w+=w*s1.w;
        a2.x+=w*s2.x; a2.y+=w*s2.y; a2.z+=w*s2.z; a2.w+=w*s2.w;
        a3.x+=w*s3.x; a3.y+=w*s3.y; a3.z+=w*s3.z; a3.w+=w*s3.w;
    }
    float4* d1 = (float4*)dst1;
    d1[0]=a0; d1[1]=a1; d1[2]=a2; d1[3]=a3;
    if (dst2){
        float4* d2 = (float4*)dst2;
        d2[0]=a0; d2[1]=a1; d2[2]=a2; d2[3]=a3;
    }
}

// ============ K1: z+r GEMM + epilogue + spconv->Au. grid (16 js, 8 q) ============
__global__ void __launch_bounds__(256,1) step_zr(const float* __restrict__ Wh, int t){
    __shared__ __align__(16) float SB[10752];   // As 32x264 = 8448, Bs 32x72 = 2304
    float* As = SB;
    float* Bs = SB + 8448;
    float* su = SB;   // overlay after GEMM
    int tid = threadIdx.x;
    int js = blockIdx.x, q = blockIdx.y;
    const float* Aq = g_Ah + ((size_t)q << 16);

    int rg = tid >> 3, cg = tid & 7;
    int arow = tid >> 3, ap4 = (tid & 7) << 2;
    int bk = tid >> 3;
    int cb = (tid & 7) << 2;
    int colbase = (cb < 16) ? (js*16 + cb) : (256 + js*16 + cb - 16);
    const float* Bg = Wh + (size_t)bk*G3 + colbase;

    u64 acc[4][4];
    #pragma unroll
    for (int i=0;i<4;i++){ acc[i][0]=0; acc[i][1]=0; acc[i][2]=0; acc[i][3]=0; }

    float4 nA[8]; float4 nB;
    #pragma unroll
    for (int i=0;i<8;i++)
        nA[i] = __ldcg((const float4*)(Aq + ((size_t)(arow+(i<<5))<<8) + ap4));
    nB = __ldg((const float4*)Bg);

    for (int kb = 0; kb < 256; kb += 32){
        #pragma unroll
        for (int i=0;i<8;i++){
            int r = arow + (i<<5);
            As[(ap4+0)*264+r]=nA[i].x; As[(ap4+1)*264+r]=nA[i].y;
            As[(ap4+2)*264+r]=nA[i].z; As[(ap4+3)*264+r]=nA[i].w;
        }
        {
            float* bp = Bs + bk*72 + (cb<<1);
            bp[0]=nB.x; bp[1]=nB.x; bp[2]=nB.y; bp[3]=nB.y;
            bp[4]=nB.z; bp[5]=nB.z; bp[6]=nB.w; bp[7]=nB.w;
        }
        __syncthreads();
        if (kb < 224){
            #pragma unroll
            for (int i=0;i<8;i++)
                nA[i] = __ldcg((const float4*)(Aq + ((size_t)(arow+(i<<5))<<8) + kb + 32 + ap4));
            nB = __ldg((const float4*)(Bg + (size_t)(kb+32)*G3));
        }
        #pragma unroll 8
        for (int k = 0; k < 32; k++){
            F4U a0,a1,b0,b1;
            a0.f = *(const float4*)(As + k*264 + rg*8);
            a1.f = *(const float4*)(As + k*264 + rg*8 + 4);
            b0.f = *(const float4*)(Bs + k*72 + cg*8);
            b1.f = *(const float4*)(Bs + k*72 + cg*8 + 4);
            u64 ar[4] = { a0.u[0], a0.u[1], a1.u[0], a1.u[1] };
            u64 bd[4] = { b0.u[0], b0.u[1], b1.u[0], b1.u[1] };
            #pragma unroll
            for (int i=0;i<4;i++){
                ffma2(acc[i][0],ar[i],bd[0]); ffma2(acc[i][1],ar[i],bd[1]);
                ffma2(acc[i][2],ar[i],bd[2]); ffma2(acc[i][3],ar[i],bd[3]);
            }
        }
        __syncthreads();
    }

    size_t gxrow0 = ((size_t)(q*TT + t))*NN;
    #pragma unroll
    for (int rp = 0; rp < 4; rp++){
        float2 c0=unpack2(acc[rp][0]), c1=unpack2(acc[rp][1]);
        float2 c2=unpack2(acc[rp][2]), c3=unpack2(acc[rp][3]);
        #pragma unroll
        for (int rr = 0; rr < 2; rr++){
            int row = rg*8 + rp*2 + rr;
            float4 v = rr==0 ? make_float4(c0.x,c1.x,c2.x,c3.x)
                             : make_float4(c0.y,c1.y,c2.y,c3.y);
            size_t gxi = (gxrow0 + row)*G3;
            size_t hrow = ((size_t)(q*NN + row))*HH;
            if (cb < 16){
                float4 g = __ldg((const float4*)(g_gx + gxi + js*16 + cb));
                float4 z4;
                z4.x=sigmoidf_(v.x+g.x); z4.y=sigmoidf_(v.y+g.y);
                z4.z=sigmoidf_(v.z+g.z); z4.w=sigmoidf_(v.w+g.w);
                *(float4*)(g_z + hrow + js*16 + cb) = z4;
            } else {
                int c04 = cb - 16;
                float4 g = __ldg((const float4*)(g_gx + gxi + 256 + js*16 + c04));
                float4 h4 = __ldcg((const float4*)(g_h + hrow + js*16 + c04));
                float4 u;
                u.x=sigmoidf_(v.x+g.x)*h4.x; u.y=sigmoidf_(v.y+g.y)*h4.y;
                u.z=sigmoidf_(v.z+g.z)*h4.z; u.w=sigmoidf_(v.w+g.w)*h4.w;
                *(float4*)(su + row*20 + c04) = u;
            }
        }
    }
    __syncthreads();
    spconv16(su, g_Au + (((size_t)(q<<8)) + tid)*HH + js*16, (float*)0);
}

// ============ K2: c GEMM + h update + spconv->Ah (+Axseq / +hseq) ============
__global__ void __launch_bounds__(256,1) step_c(const float* __restrict__ Wh, int t,
                                                int writeAx, int writeHseq){
    __shared__ __align__(16) float SB[9600];    // As 32x264 = 8448, Bs 32x36 = 1152
    float* As = SB;
    float* Bs = SB + 8448;
    float* su = SB;
    int tid = threadIdx.x;
    int js = blockIdx.x, q = blockIdx.y;
    const float* Aq = g_Au + ((size_t)q << 16);

    int rg = tid >> 3, cg = tid & 7;
    int arow = tid >> 3, ap4 = (tid & 7) << 2;
    int bk = tid >> 3;
    int c2 = (tid & 7) << 1;
    const float* Bg = Wh + (size_t)bk*G3 + 512 + js*16 + c2;

    u64 acc[4][2];
    #pragma unroll
    for (int i=0;i<4;i++){ acc[i][0]=0; acc[i][1]=0; }

    float4 nA[8]; float2 nB;
    #pragma unroll
    for (int i=0;i<8;i++)
        nA[i] = __ldcg((const float4*)(Aq + ((size_t)(arow+(i<<5))<<8) + ap4));
    nB = __ldg((const float2*)Bg);

    for (int kb = 0; kb < 256; kb += 32){
        #pragma unroll
        for (int i=0;i<8;i++){
            int r = arow + (i<<5);
            As[(ap4+0)*264+r]=nA[i].x; As[(ap4+1)*264+r]=nA[i].y;
            As[(ap4+2)*264+r]=nA[i].z; As[(ap4+3)*264+r]=nA[i].w;
        }
        {
            float* bp = Bs + bk*36 + (c2<<1);
            bp[0]=nB.x; bp[1]=nB.x; bp[2]=nB.y; bp[3]=nB.y;
        }
        __syncthreads();
        if (kb < 224){
            #pragma unroll
            for (int i=0;i<8;i++)
                nA[i] = __ldcg((const float4*)(Aq + ((size_t)(arow+(i<<5))<<8) + kb + 32 + ap4));
            nB = __ldg((const float2*)(Bg + (size_t)(kb+32)*G3));
        }
        #pragma unroll 8
        for (int k = 0; k < 32; k++){
            F4U a0,a1,b0;
            a0.f = *(const float4*)(As + k*264 + rg*8);
            a1.f = *(const float4*)(As + k*264 + rg*8 + 4);
            b0.f = *(const float4*)(Bs + k*36 + cg*4);
            u64 ar[4] = { a0.u[0], a0.u[1], a1.u[0], a1.u[1] };
            #pragma unroll
            for (int i=0;i<4;i++){
                ffma2(acc[i][0],ar[i],b0.u[0]);
                ffma2(acc[i][1],ar[i],b0.u[1]);
            }
        }
        __syncthreads();
    }

    size_t gxrow0 = ((size_t)(q*TT + t))*NN;
    #pragma unroll
    for (int rp = 0; rp < 4; rp++){
        float2 p0=unpack2(acc[rp][0]), p1=unpack2(acc[rp][1]);
        #pragma unroll
        for (int rr = 0; rr < 2; rr++){
            int row = rg*8 + rp*2 + rr;
            float2 v = rr==0 ? make_float2(p0.x,p1.x) : make_float2(p0.y,p1.y);
            size_t gxi = (gxrow0 + row)*G3;
            size_t hrow = ((size_t)(q*NN + row))*HH;
            int col = js*16 + c2;
            float2 g  = __ldg((const float2*)(g_gx + gxi + 512 + col));
            float2 z2 = __ldcg((const float2*)(g_z + hrow + col));
            float2 h2 = __ldcg((const float2*)(g_h + hrow + col));
            float2 hn;
            hn.x = z2.x*h2.x + (1.0f - z2.x)*tanhf(v.x + g.x);
            hn.y = z2.y*h2.y + (1.0f - z2.y)*tanhf(v.y + g.y);
            *(float2*)(g_h + hrow + col) = hn;
            if (writeHseq) *(float2*)(g_hseq + (gxrow0 + row)*HH + col) = hn;
            *(float2*)(su + row*20 + c2) = hn;
        }
    }
    __syncthreads();
    float* ax2 = writeAx ? (g_Axseq + (gxrow0 + tid)*HH + js*16) : (float*)0;
    spconv16(su, g_Ah + (((size_t)(q<<8)) + tid)*HH + js*16, ax2);
}

// ---------------- layer-1 gx GEMM: g_gx = g_Axseq @ Wx1 + b1 ----------------
__global__ void __launch_bounds__(256, 2) gemm_gx1(const float* __restrict__ Wx1,
                                                   const float* __restrict__ b1){
    __shared__ __align__(16) float sA[2048];
    __shared__ __align__(16) float sB[4096];
    int tid = threadIdx.x;
    int r0 = blockIdx.y << 7;
    int j0 = blockIdx.x << 7;
    int lrow = tid >> 1, lk = (tid & 1) << 3;
    int bk = tid >> 4, bc = (tid & 15) << 3;
    int ty = tid >> 4, tx = tid & 15;

    u64 acc[4][8];
    #pragma unroll
    for (int i=0;i<4;i++)
        #pragma unroll
        for (int j=0;j<8;j++) acc[i][j]=0;

    const float* ag = g_Axseq + (size_t)(r0 + lrow)*HH + lk;
    const float* bg = Wx1 + (size_t)bk*G3 + j0 + bc;

    float4 a0 = __ldg((const float4*)ag);
    float4 a1 = __ldg((const float4*)(ag + 4));
    float4 b0 = __ldg((const float4*)bg);
    float4 b1v = __ldg((const float4*)(bg + 4));

    for (int kc = 0; kc < 256; kc += 16){
        sA[(lk+0)*128+lrow]=a0.x; sA[(lk+1)*128+lrow]=a0.y;
        sA[(lk+2)*128+lrow]=a0.z; sA[(lk+3)*128+lrow]=a0.w;
        sA[(lk+4)*128+lrow]=a1.x; sA[(lk+5)*128+lrow]=a1.y;
        sA[(lk+6)*128+lrow]=a1.z; sA[(lk+7)*128+lrow]=a1.w;
        float* sbp = sB + bk*256 + bc*2;
        ((float4*)sbp)[0]=make_float4(b0.x,b0.x,b0.y,b0.y);
        ((float4*)sbp)[1]=make_float4(b0.z,b0.z,b0.w,b0.w);
        ((float4*)sbp)[2]=make_float4(b1v.x,b1v.x,b1v.y,b1v.y);
        ((float4*)sbp)[3]=make_float4(b1v.z,b1v.z,b1v.w,b1v.w);
        __syncthreads();
        if (kc + 16 < 256){
            a0 = __ldg((const float4*)(ag + kc + 16));
            a1 = __ldg((const float4*)(ag + kc + 20));
            const float* bg2 = bg + (size_t)(kc + 16)*G3;
            b0 = __ldg((const float4*)bg2);
            b1v = __ldg((const float4*)(bg2 + 4));
        }
        #pragma unroll
        for (int p = 0; p < 16; p++){
            F4U ta0, ta1;
            ta0.f = *(const float4*)(sA + p*128 + ty*8);
            ta1.f = *(const float4*)(sA + p*128 + ty*8 + 4);
            u64 ar[4] = { ta0.u[0], ta0.u[1], ta1.u[0], ta1.u[1] };
            F4U tb0,tb1,tb2,tb3;
            tb0.f = *(const float4*)(sB + p*256 + tx*16);
            tb1.f = *(const float4*)(sB + p*256 + tx*16 + 4);
            tb2.f = *(const float4*)(sB + p*256 + tx*16 + 8);
            tb3.f = *(const float4*)(sB + p*256 + tx*16 + 12);
            u64 bd[8] = { tb0.u[0],tb0.u[1],tb1.u[0],tb1.u[1],
                          tb2.u[0],tb2.u[1],tb3.u[0],tb3.u[1] };
            #pragma unroll
            for (int i=0;i<4;i++)
                #pragma unroll
                for (int j=0;j<8;j++) ffma2(acc[i][j],ar[i],bd[j]);
        }
        __syncthreads();
    }

    float bb[8];
    #pragma unroll
    for (int j=0;j<8;j++) bb[j] = b1[j0 + tx*8 + j];
    #pragma unroll
    for (int i=0;i<4;i++){
        float2 c[8];
        #pragma unroll
        for (int j=0;j<8;j++){ c[j]=unpack2(acc[i][j]); c[j].x+=bb[j]; c[j].y+=bb[j]; }
        float* rp = g_gx + (size_t)(r0 + ty*8 + 2*i)*G3 + j0 + tx*8;
        *(float4*)rp        = make_float4(c[0].x,c[1].x,c[2].x,c[3].x);
        *(float4*)(rp+4)    = make_float4(c[4].x,c[5].x,c[6].x,c[7].x);
        *(float4*)(rp+G3)   = make_float4(c[0].y,c[1].y,c[2].y,c[3].y);
        *(float4*)(rp+G3+4) = make_float4(c[4].y,c[5].y,c[6].y,c[7].y);
    }
}

// ---------------- output head ----------------
__global__ void out_head(const float* __restrict__ Wout, const float* __restrict__ bout,
                         float* __restrict__ out){
    __shared__ float sh[32*257];
    __shared__ float Ws[HH*DO];
    __shared__ float bs[DO];
    int r0 = blockIdx.x * 32;
    int tid = threadIdx.x;
    for (int i = tid; i < HH*DO; i += 256) Ws[i] = Wout[i];
    if (tid < DO) bs[tid] = bout[tid];
    const float4* H4 = (const float4*)g_hseq;
    for (int i = tid; i < 32*64; i += 256){
        int rr = i >> 6, c4 = i & 63;
        float4 v = H4[((size_t)(r0 + rr))*64 + c4];
        float* dst = &sh[rr*257 + c4*4];
        dst[0]=v.x; dst[1]=v.y; dst[2]=v.z; dst[3]=v.w;
    }
    __syncthreads();
    for (int oi = tid; oi < 32*DO; oi += 256){
        int rr = oi / DO, c = oi % DO;
        float a0 = bs[c], a1 = 0.0f;
        const float* sr = &sh[rr*257];
        for (int k = 0; k < HH; k += 2){
            a0 += sr[k]   * Ws[k*DO + c];
            a1 += sr[k+1] * Ws[(k+1)*DO + c];
        }
        out[(size_t)(r0 + rr)*DO + c] = a0 + a1;
    }
}

// ---------------- launch ----------------
extern "C" void kernel_launch(void* const* d_in, const int* in_sizes, int n_in,
                              void* d_out, int out_size) {
    const float* x2d  = (const float*)d_in[0];
    const float* mask = (const float*)d_in[1];
    const float* adj  = (const float*)d_in[2];
    const float* Wx0  = (const float*)d_in[3];
    const float* Wh0  = (const float*)d_in[4];
    const float* b0   = (const float*)d_in[5];
    const float* Wx1  = (const float*)d_in[6];
    const float* Wh1  = (const float*)d_in[7];
    const float* b1   = (const float*)d_in[8];
    const float* Wout = (const float*)d_in[9];
    const float* bout = (const float*)d_in[10];
    float* out = (float*)d_out;

    build_csr<<<1, 256>>>(adj);
    prep_gx0<<<BB*TT, 256>>>(x2d, mask, Wx0, b0);

    // layer 0 (step_c also emits g_Axseq inline)
    zero_hAh<<<512, 256>>>();
    for (int t = 0; t < TT; t++){
        step_zr<<<dim3(16, BB), 256>>>(Wh0, t);
        step_c <<<dim3(16, BB), 256>>>(Wh0, t, 1, 0);
    }

    gemm_gx1<<<dim3(6, (BB*TT*NN)/128), 256>>>(Wx1, b1);

    // layer 1 (writes hseq for output head)
    zero_hAh<<<512, 256>>>();
    for (int t = 0; t < TT; t++){
        step_zr<<<dim3(16, BB), 256>>>(Wh1, t);
        step_c <<<dim3(16, BB), 256>>>(Wh1, t, 0, 1);
    }

    out_head<<<(BB*TT*NN)/32, 256>>>(Wout, bout, out);
}

// round 9
// speedup vs baseline: 1.1317x; 1.1317x over previous
#include <cuda_runtime.h>
#include <math.h>

#define BB 8
#define TT 64
#define NN 256
#define HH 256
#define DI 6
#define DO 9
#define G3 (3*HH)   // 768

typedef unsigned long long u64;

// ---------------- scratch (device globals; no runtime allocation) ----------------
__device__ __align__(16) float g_gx[(size_t)BB*TT*NN*G3];
__device__ __align__(16) float g_hseq[(size_t)BB*TT*NN*HH];
__device__ __align__(16) float g_Axseq[(size_t)BB*TT*NN*HH];
__device__ __align__(16) float g_h [BB*NN*HH];
__device__ __align__(16) float g_Ah[BB*NN*HH];
__device__ __align__(16) float g_z [BB*NN*HH];
__device__ __align__(16) float g_u [BB*NN*HH];
__device__ __align__(16) float g_Au[BB*NN*HH];
__device__ int   g_cnt[NN];
__device__ int   g_col[NN*NN];
__device__ float g_val[NN*NN];

union F4U { float4 f; u64 u[2]; };

__device__ __forceinline__ void ffma2(u64& d, u64 a, u64 b){
    asm("fma.rn.f32x2 %0, %1, %2, %0;" : "+l"(d) : "l"(a), "l"(b));
}
__device__ __forceinline__ float2 unpack2(u64 v){
    float2 f; asm("mov.b64 {%0, %1}, %2;" : "=f"(f.x), "=f"(f.y) : "l"(v)); return f;
}
__device__ __forceinline__ float sigmoidf_(float x){ return 1.0f / (1.0f + expf(-x)); }

// ---------------- CSR build from dense adjacency (zeros are exact) ----------------
__global__ void build_csr(const float* __restrict__ adj){
    int n = threadIdx.x;
    int c = 0;
    for (int m = 0; m < NN; m++){
        float v = adj[n*NN + m];
        if (v != 0.0f){ g_col[n*NN + c] = m; g_val[n*NN + c] = v; c++; }
    }
    g_cnt[n] = c;
}

__global__ void zero_h(){
    int i = blockIdx.x * 256 + threadIdx.x;
    g_h[i] = 0.0f;
}

// ---------------- layer-0 gx: per (b,t), gx = (A (x) (x*mask)) @ Wx0 + b0 ----------------
__global__ void prep_gx0(const float* __restrict__ x2d, const float* __restrict__ mask,
                         const float* __restrict__ Wx0, const float* __restrict__ b0){
    __shared__ float xm[NN*DI];
    __shared__ float ax[NN*DI];
    __shared__ float Ws[DI*G3];
    int bt = blockIdx.x;
    int tid = threadIdx.x;

    for (int i = tid; i < NN*DI; i += 256){
        int n = i / DI;
        xm[i] = x2d[(size_t)bt*NN*DI + i] * mask[(size_t)bt*NN + n];
    }
    for (int i = tid; i < DI*G3; i += 256) Ws[i] = Wx0[i];
    __syncthreads();

    {   // sparse conv: one node per thread
        int n = tid;
        float a0=0,a1=0,a2=0,a3=0,a4=0,a5=0;
        int cn = g_cnt[n];
        for (int e = 0; e < cn; e++){
            int m = g_col[n*NN + e];
            float w = g_val[n*NN + e];
            const float* xr = xm + m*DI;
            a0 += w*xr[0]; a1 += w*xr[1]; a2 += w*xr[2];
            a3 += w*xr[3]; a4 += w*xr[4]; a5 += w*xr[5];
        }
        float* ar = ax + n*DI;
        ar[0]=a0; ar[1]=a1; ar[2]=a2; ar[3]=a3; ar[4]=a4; ar[5]=a5;
    }
    __syncthreads();

    for (int jj = 0; jj < 3; jj++){
        int j = tid + (jj << 8);
        float w0=Ws[j], w1=Ws[G3+j], w2=Ws[2*G3+j], w3=Ws[3*G3+j], w4=Ws[4*G3+j], w5=Ws[5*G3+j];
        float bj = b0[j];
        float* gout = g_gx + (size_t)bt*NN*G3 + j;
        for (int n = 0; n < NN; n++){
            const float* axr = ax + n*DI;
            float s = bj + axr[0]*w0 + axr[1]*w1 + axr[2]*w2
                         + axr[3]*w3 + axr[4]*w4 + axr[5]*w5;
            gout[(size_t)n*G3] = s;
        }
    }
}

// ---------------- smem spconv (R2-proven): pitch 20, 16 cols ----------------
__device__ __forceinline__ void spconv16(const float* su, float* dst1){
    int n = threadIdx.x;
    float4 a0 = make_float4(0,0,0,0), a1 = a0, a2 = a0, a3 = a0;
    int cn = g_cnt[n];
    const int*   cp = g_col + n*NN;
    const float* vp = g_val + n*NN;
    for (int e = 0; e < cn; e++){
        int m = cp[e]; float w = vp[e];
        const float4* sm = (const float4*)(su + m*20);
        float4 s0=sm[0], s1=sm[1], s2=sm[2], s3=sm[3];
        a0.x+=w*s0.x; a0.y+=w*s0.y; a0.z+=w*s0.z; a0.w+=w*s0.w;
        a1.x+=w*s1.x; a1.y+=w*s1.y; a1.z+=w*s1.z; a1.w+=w*s1.w;
        a2.x+=w*s2.x; a2.y+=w*s2.y; a2.z+=w*s2.z; a2.w+=w*s2.w;
        a3.x+=w*s3.x; a3.y+=w*s3.y; a3.z+=w*s3.z; a3.w+=w*s3.w;
    }
    float4* d1 = (float4*)(dst1 + (size_t)n*HH);
    d1[0]=a0; d1[1]=a1; d1[2]=a2; d1[3]=a3;
}

// ---------------- per-step conv: which=0: Ah=A(x)h; which=1: Au=A(x)u ----------------
// grid (16 js, 8 q). Device globals selected INSIDE the kernel (host cannot pass them).
__global__ void __launch_bounds__(256,1) conv_in(int which){
    __shared__ __align__(16) float su[256*20];
    const float* __restrict__ X = which ? g_u  : g_h;
    float* __restrict__       Y = which ? g_Au : g_Ah;
    int js = blockIdx.x, q = blockIdx.y, n = threadIdx.x;
    const float4* xp = (const float4*)(X + ((size_t)(q<<8) + n)*HH + (js<<4));
    float4* s = (float4*)(su + n*20);
    s[0] = __ldcg(xp);
    s[1] = __ldcg(xp+1);
    s[2] = __ldcg(xp+2);
    s[3] = __ldcg(xp+3);
    __syncthreads();
    spconv16(su, Y + ((size_t)(q<<8))*HH + (js<<4));
}

// ---------------- R1-proven 64x64x16 fp32 GEMM body ----------------
#define GEMM64x64(ABASE, ALd, BBASE, BLd)                                           \
    do {                                                                            \
        for (int kk = 0; kk < HH; kk += 16){                                        \
            float4 av = *(const float4*)((ABASE) + (size_t)(r0+li)*(ALd) + kk + lp4); \
            As[lp4+0][li]=av.x; As[lp4+1][li]=av.y; As[lp4+2][li]=av.z; As[lp4+3][li]=av.w; \
            float4 bv = *(const float4*)((BBASE) + (size_t)(kk+bp)*(BLd) + bj4);    \
            *(float4*)&Bs[bp][bj4] = bv;                                            \
            __syncthreads();                                                        \
            _Pragma("unroll")                                                       \
            for (int p = 0; p < 16; p++){                                           \
                float4 a = *(const float4*)&As[p][ty*4];                            \
                float4 b = *(const float4*)&Bs[p][tx*4];                            \
                acc[0][0]+=a.x*b.x; acc[0][1]+=a.x*b.y; acc[0][2]+=a.x*b.z; acc[0][3]+=a.x*b.w; \
                acc[1][0]+=a.y*b.x; acc[1][1]+=a.y*b.y; acc[1][2]+=a.y*b.z; acc[1][3]+=a.y*b.w; \
                acc[2][0]+=a.z*b.x; acc[2][1]+=a.z*b.y; acc[2][2]+=a.z*b.z; acc[2][3]+=a.z*b.w; \
                acc[3][0]+=a.w*b.x; acc[3][1]+=a.w*b.y; acc[3][2]+=a.w*b.z; acc[3][3]+=a.w*b.w; \
            }                                                                       \
            __syncthreads();                                                        \
        }                                                                           \
    } while(0)

#define GEMM_PROLOGUE                          \
    __shared__ float As[16][64];               \
    __shared__ float Bs[16][64];               \
    int tid = threadIdx.x;                     \
    int r0 = blockIdx.y * 64;                  \
    int j0 = blockIdx.x * 64;                  \
    int ty = tid >> 4, tx = tid & 15;          \
    int li = tid >> 2;                         \
    int lp4 = (tid & 3) * 4;                   \
    int bp = tid >> 4;                         \
    int bj4 = (tid & 15) * 4;                  \
    float acc[4][4] = {};

// z/r gates: gzr = Ah @ Wh[:, :512] + gx[:, :512]; z=sig, r=sig, u=r*h
__global__ void gemm_zr(const float* __restrict__ Wh, int t){
    GEMM_PROLOGUE
    GEMM64x64(g_Ah, HH, Wh + j0, G3);
    #pragma unroll
    for (int ii = 0; ii < 4; ii++)
    #pragma unroll
    for (int jj = 0; jj < 4; jj++){
        int r = r0 + ty*4 + ii;
        int j = j0 + tx*4 + jj;
        int b = r >> 8, n = r & 255;
        float val = acc[ii][jj] + g_gx[(((size_t)(b*TT + t))*NN + n)*G3 + j];
        if (j < HH){
            g_z[(size_t)r*HH + j] = sigmoidf_(val);
        } else {
            int j2 = j - HH;
            float rr = sigmoidf_(val);
            g_u[(size_t)r*HH + j2] = rr * g_h[(size_t)r*HH + j2];
        }
    }
}

// c gate + state update: c = tanh(Au @ Wh[:,512:] + gx[:,512:]); h = z*h + (1-z)*c
__global__ void gemm_c(const float* __restrict__ Wh, int t){
    GEMM_PROLOGUE
    GEMM64x64(g_Au, HH, Wh + 512 + j0, G3);
    #pragma unroll
    for (int ii = 0; ii < 4; ii++)
    #pragma unroll
    for (int jj = 0; jj < 4; jj++){
        int r = r0 + ty*4 + ii;
        int j = j0 + tx*4 + jj;
        int b = r >> 8, n = r & 255;
        float val = acc[ii][jj] + g_gx[(((size_t)(b*TT + t))*NN + n)*G3 + 512 + j];
        float c = tanhf(val);
        size_t idx = (size_t)r*HH + j;
        float zv = g_z[idx];
        float hn = zv * g_h[idx] + (1.0f - zv) * c;
        g_h[idx] = hn;
        g_hseq[(((size_t)(b*TT + t))*NN + n)*HH + j] = hn;
    }
}

// ---------------- sequence sparse conv (R1-proven): g_Axseq = A (x) g_hseq ----------------
__global__ void spconv_seq(){
    __shared__ float Xs[NN*32];
    int kh = blockIdx.x;       // 0..7
    int q  = blockIdx.y;       // 0..511
    int tid = threadIdx.x;
    const float4* X4 = (const float4*)g_hseq;
    float4* Xs4 = (float4*)Xs;
    for (int i = tid; i < NN*8; i += 256){
        int m = i >> 3, c4 = i & 7;
        Xs4[i] = X4[((size_t)q*NN + m)*64 + kh*8 + c4];
    }
    __syncthreads();
    int k  = tid & 31;
    int ng = tid >> 5;         // 0..7
    for (int nb = 0; nb < NN; nb += 8){
        int n = nb + ng;
        int cn = g_cnt[n];
        const int*   cp = g_col + n*NN;
        const float* vp = g_val + n*NN;
        float a0 = 0.0f, a1 = 0.0f;
        int e = 0;
        for (; e + 2 <= cn; e += 2){
            a0 += vp[e]   * Xs[(cp[e]   << 5) + k];
            a1 += vp[e+1] * Xs[(cp[e+1] << 5) + k];
        }
        if (e < cn) a0 += vp[e] * Xs[(cp[e] << 5) + k];
        g_Axseq[((size_t)q*NN + n)*HH + (kh << 5) + k] = a0 + a1;
    }
}

// ---------------- layer-1 gx GEMM (R3/R4-proven f32x2): g_gx = g_Axseq @ Wx1 + b1 ----------------
__global__ void __launch_bounds__(256, 2) gemm_gx1(const float* __restrict__ Wx1,
                                                   const float* __restrict__ b1){
    __shared__ __align__(16) float sA[2048];
    __shared__ __align__(16) float sB[4096];
    int tid = threadIdx.x;
    int r0 = blockIdx.y << 7;
    int j0 = blockIdx.x << 7;
    int lrow = tid >> 1, lk = (tid & 1) << 3;
    int bk = tid >> 4, bc = (tid & 15) << 3;
    int ty = tid >> 4, tx = tid & 15;

    u64 acc[4][8];
    #pragma unroll
    for (int i=0;i<4;i++)
        #pragma unroll
        for (int j=0;j<8;j++) acc[i][j]=0;

    const float* ag = g_Axseq + (size_t)(r0 + lrow)*HH + lk;
    const float* bg = Wx1 + (size_t)bk*G3 + j0 + bc;

    float4 a0 = __ldg((const float4*)ag);
    float4 a1 = __ldg((const float4*)(ag + 4));
    float4 b0 = __ldg((const float4*)bg);
    float4 b1v = __ldg((const float4*)(bg + 4));

    for (int kc = 0; kc < 256; kc += 16){
        sA[(lk+0)*128+lrow]=a0.x; sA[(lk+1)*128+lrow]=a0.y;
        sA[(lk+2)*128+lrow]=a0.z; sA[(lk+3)*128+lrow]=a0.w;
        sA[(lk+4)*128+lrow]=a1.x; sA[(lk+5)*128+lrow]=a1.y;
        sA[(lk+6)*128+lrow]=a1.z; sA[(lk+7)*128+lrow]=a1.w;
        float* sbp = sB + bk*256 + bc*2;
        ((float4*)sbp)[0]=make_float4(b0.x,b0.x,b0.y,b0.y);
        ((float4*)sbp)[1]=make_float4(b0.z,b0.z,b0.w,b0.w);
        ((float4*)sbp)[2]=make_float4(b1v.x,b1v.x,b1v.y,b1v.y);
        ((float4*)sbp)[3]=make_float4(b1v.z,b1v.z,b1v.w,b1v.w);
        __syncthreads();
        if (kc + 16 < 256){
            a0 = __ldg((const float4*)(ag + kc + 16));
            a1 = __ldg((const float4*)(ag + kc + 20));
            const float* bg2 = bg + (size_t)(kc + 16)*G3;
            b0 = __ldg((const float4*)bg2);
            b1v = __ldg((const float4*)(bg2 + 4));
        }
        #pragma unroll
        for (int p = 0; p < 16; p++){
            F4U ta0, ta1;
            ta0.f = *(const float4*)(sA + p*128 + ty*8);
            ta1.f = *(const float4*)(sA + p*128 + ty*8 + 4);
            u64 ar[4] = { ta0.u[0], ta0.u[1], ta1.u[0], ta1.u[1] };
            F4U tb0,tb1,tb2,tb3;
            tb0.f = *(const float4*)(sB + p*256 + tx*16);
            tb1.f = *(const float4*)(sB + p*256 + tx*16 + 4);
            tb2.f = *(const float4*)(sB + p*256 + tx*16 + 8);
            tb3.f = *(const float4*)(sB + p*256 + tx*16 + 12);
            u64 bd[8] = { tb0.u[0],tb0.u[1],tb1.u[0],tb1.u[1],
                          tb2.u[0],tb2.u[1],tb3.u[0],tb3.u[1] };
            #pragma unroll
            for (int i=0;i<4;i++)
                #pragma unroll
                for (int j=0;j<8;j++) ffma2(acc[i][j],ar[i],bd[j]);
        }
        __syncthreads();
    }

    float bb[8];
    #pragma unroll
    for (int j=0;j<8;j++) bb[j] = b1[j0 + tx*8 + j];
    #pragma unroll
    for (int i=0;i<4;i++){
        float2 c[8];
        #pragma unroll
        for (int j=0;j<8;j++){ c[j]=unpack2(acc[i][j]); c[j].x+=bb[j]; c[j].y+=bb[j]; }
        float* rp = g_gx + (size_t)(r0 + ty*8 + 2*i)*G3 + j0 + tx*8;
        *(float4*)rp        = make_float4(c[0].x,c[1].x,c[2].x,c[3].x);
        *(float4*)(rp+4)    = make_float4(c[4].x,c[5].x,c[6].x,c[7].x);
        *(float4*)(rp+G3)   = make_float4(c[0].y,c[1].y,c[2].y,c[3].y);
        *(float4*)(rp+G3+4) = make_float4(c[4].y,c[5].y,c[6].y,c[7].y);
    }
}

// ---------------- output head (R1-proven) ----------------
__global__ void out_head(const float* __restrict__ Wout, const float* __restrict__ bout,
                         float* __restrict__ out){
    __shared__ float sh[32*257];
    __shared__ float Ws[HH*DO];
    __shared__ float bs[DO];
    int r0 = blockIdx.x * 32;
    int tid = threadIdx.x;
    for (int i = tid; i < HH*DO; i += 256) Ws[i] = Wout[i];
    if (tid < DO) bs[tid] = bout[tid];
    const float4* H4 = (const float4*)g_hseq;
    for (int i = tid; i < 32*64; i += 256){
        int rr = i >> 6, c4 = i & 63;
        float4 v = H4[((size_t)(r0 + rr))*64 + c4];
        float* dst = &sh[rr*257 + c4*4];
        dst[0]=v.x; dst[1]=v.y; dst[2]=v.z; dst[3]=v.w;
    }
    __syncthreads();
    for (int oi = tid; oi < 32*DO; oi += 256){
        int rr = oi / DO, c = oi % DO;
        float a0 = bs[c], a1 = 0.0f;
        const float* sr = &sh[rr*257];
        for (int k = 0; k < HH; k += 2){
            a0 += sr[k]   * Ws[k*DO + c];
            a1 += sr[k+1] * Ws[(k+1)*DO + c];
        }
        out[(size_t)(r0 + rr)*DO + c] = a0 + a1;
    }
}

// ---------------- launch (R1 orchestration; spconv_step -> conv_in) ----------------
extern "C" void kernel_launch(void* const* d_in, const int* in_sizes, int n_in,
                              void* d_out, int out_size) {
    const float* x2d  = (const float*)d_in[0];
    const float* mask = (const float*)d_in[1];
    const float* adj  = (const float*)d_in[2];
    const float* Wx0  = (const float*)d_in[3];
    const float* Wh0  = (const float*)d_in[4];
    const float* b0   = (const float*)d_in[5];
    const float* Wx1  = (const float*)d_in[6];
    const float* Wh1  = (const float*)d_in[7];
    const float* b1   = (const float*)d_in[8];
    const float* Wout = (const float*)d_in[9];
    const float* bout = (const float*)d_in[10];
    float* out = (float*)d_out;

    build_csr<<<1, 256>>>(adj);
    prep_gx0<<<BB*TT, 256>>>(x2d, mask, Wx0, b0);

    // ---- layer 0 recurrence ----
    zero_h<<<2048, 256>>>();
    for (int t = 0; t < TT; t++){
        conv_in<<<dim3(16, BB), 256>>>(0);
        gemm_zr<<<dim3(8, (BB*NN)/64), 256>>>(Wh0, t);
        conv_in<<<dim3(16, BB), 256>>>(1);
        gemm_c<<<dim3(4, (BB*NN)/64), 256>>>(Wh0, t);
    }

    // ---- layer 1 gx precompute (parallel over all t) ----
    spconv_seq<<<dim3(8, BB*TT), 256>>>();
    gemm_gx1<<<dim3(6, (BB*TT*NN)/128), 256>>>(Wx1, b1);

    // ---- layer 1 recurrence ----
    zero_h<<<2048, 256>>>();
    for (int t = 0; t < TT; t++){
        conv_in<<<dim3(16, BB), 256>>>(0);
        gemm_zr<<<dim3(8, (BB*NN)/64), 256>>>(Wh1, t);
        conv_in<<<dim3(16, BB), 256>>>(1);
        gemm_c<<<dim3(4, (BB*NN)/64), 256>>>(Wh1, t);
    }

    // ---- output head ----
    out_head<<<(BB*TT*NN)/32, 256>>>(Wout, bout, out);
}

// round 10
// speedup vs baseline: 1.3970x; 1.2345x over previous
#include <cuda_runtime.h>
#include <math.h>

#define BB 8
#define TT 64
#define NN 256
#define HH 256
#define DI 6
#define DO 9
#define G3 (3*HH)   // 768

typedef unsigned long long u64;

// ---------------- scratch (device globals; no runtime allocation) ----------------
__device__ __align__(16) float g_gx[(size_t)BB*TT*NN*G3];
__device__ __align__(16) float g_hseq[(size_t)BB*TT*NN*HH];
__device__ __align__(16) float g_Axseq[(size_t)BB*TT*NN*HH];
__device__ __align__(16) float g_h [BB*NN*HH];
__device__ __align__(16) float g_Ah[BB*NN*HH];
__device__ __align__(16) float g_z [BB*NN*HH];
__device__ __align__(16) float g_u [BB*NN*HH];
__device__ __align__(16) float g_Au[BB*NN*HH];
__device__ int   g_cnt[NN];
__device__ int   g_col[NN*NN];
__device__ float g_val[NN*NN];

union F4U { float4 f; u64 u[2]; };

__device__ __forceinline__ void ffma2(u64& d, u64 a, u64 b){
    asm("fma.rn.f32x2 %0, %1, %2, %0;" : "+l"(d) : "l"(a), "l"(b));
}
__device__ __forceinline__ float2 unpack2(u64 v){
    float2 f; asm("mov.b64 {%0, %1}, %2;" : "=f"(f.x), "=f"(f.y) : "l"(v)); return f;
}
__device__ __forceinline__ float sigmoidf_(float x){ return 1.0f / (1.0f + expf(-x)); }

// ---------------- CSR build from dense adjacency (zeros are exact) ----------------
__global__ void build_csr(const float* __restrict__ adj){
    int n = threadIdx.x;
    int c = 0;
    for (int m = 0; m < NN; m++){
        float v = adj[n*NN + m];
        if (v != 0.0f){ g_col[n*NN + c] = m; g_val[n*NN + c] = v; c++; }
    }
    g_cnt[n] = c;
}

__global__ void zero_h(){
    int i = blockIdx.x * 256 + threadIdx.x;
    g_h[i] = 0.0f;
}

// ---------------- layer-0 gx: per (b,t), gx = (A (x) (x*mask)) @ Wx0 + b0 ----------------
__global__ void prep_gx0(const float* __restrict__ x2d, const float* __restrict__ mask,
                         const float* __restrict__ Wx0, const float* __restrict__ b0){
    __shared__ float xm[NN*DI];
    __shared__ float ax[NN*DI];
    __shared__ float Ws[DI*G3];
    int bt = blockIdx.x;
    int tid = threadIdx.x;

    for (int i = tid; i < NN*DI; i += 256){
        int n = i / DI;
        xm[i] = x2d[(size_t)bt*NN*DI + i] * mask[(size_t)bt*NN + n];
    }
    for (int i = tid; i < DI*G3; i += 256) Ws[i] = Wx0[i];
    __syncthreads();

    {   // sparse conv: one node per thread
        int n = tid;
        float a0=0,a1=0,a2=0,a3=0,a4=0,a5=0;
        int cn = g_cnt[n];
        for (int e = 0; e < cn; e++){
            int m = g_col[n*NN + e];
            float w = g_val[n*NN + e];
            const float* xr = xm + m*DI;
            a0 += w*xr[0]; a1 += w*xr[1]; a2 += w*xr[2];
            a3 += w*xr[3]; a4 += w*xr[4]; a5 += w*xr[5];
        }
        float* ar = ax + n*DI;
        ar[0]=a0; ar[1]=a1; ar[2]=a2; ar[3]=a3; ar[4]=a4; ar[5]=a5;
    }
    __syncthreads();

    for (int jj = 0; jj < 3; jj++){
        int j = tid + (jj << 8);
        float w0=Ws[j], w1=Ws[G3+j], w2=Ws[2*G3+j], w3=Ws[3*G3+j], w4=Ws[4*G3+j], w5=Ws[5*G3+j];
        float bj = b0[j];
        float* gout = g_gx + (size_t)bt*NN*G3 + j;
        for (int n = 0; n < NN; n++){
            const float* axr = ax + n*DI;
            float s = bj + axr[0]*w0 + axr[1]*w1 + axr[2]*w2
                         + axr[3]*w3 + axr[4]*w4 + axr[5]*w5;
            gout[(size_t)n*G3] = s;
        }
    }
}

// ---------------- per-step sparse conv (R1-proven): C[q,n,:] = sum_e w * X[q,col,:] ----------------
__global__ void spconv_step(int which){
    const float* __restrict__ X = which ? g_u  : g_h;
    float* __restrict__       C = which ? g_Au : g_Ah;
    int n = blockIdx.x & 255;
    int q = blockIdx.x >> 8;
    int k = threadIdx.x;
    int cn = g_cnt[n];
    const int*   cp = g_col + n*NN;
    const float* vp = g_val + n*NN;
    const float* Xb = X + (size_t)q*NN*HH + k;
    float a0 = 0.0f, a1 = 0.0f;
    int e = 0;
    for (; e + 2 <= cn; e += 2){
        a0 += vp[e]   * Xb[cp[e]   << 8];
        a1 += vp[e+1] * Xb[cp[e+1] << 8];
    }
    if (e < cn) a0 += vp[e] * Xb[cp[e] << 8];
    C[(size_t)q*NN*HH + (n << 8) + k] = a0 + a1;
}

// ---------------- NEW: f32x2 64x64-tile fused gate GEMM ----------------
// CGATE=0: C = Ah @ Wh[:, :512]; epilogue z=sig -> g_z (j0<256) / u=sig(r)*h -> g_u (j0>=256)
// CGATE=1: C = Au @ Wh[:, 512:]; epilogue c=tanh; h = z*h+(1-z)*c -> g_h, g_hseq
// Buffers selected INSIDE kernel; only Wh (harness ptr) and t passed from host.
template<int CGATE>
__global__ void __launch_bounds__(256,2) gemm_gate(const float* __restrict__ Wh, int t){
    __shared__ __align__(16) float sA[16*68];    // [k][row], padded
    __shared__ __align__(16) float sB[16*132];   // [k][dup cols: lo 64 | hi 64]
    int tid = threadIdx.x;
    int j0 = blockIdx.x << 6;
    int r0 = blockIdx.y << 6;
    int ty = tid >> 4, tx = tid & 15;
    int lrow = tid >> 2, lk4 = (tid & 3) << 2;
    int bk = tid >> 4, bc4 = (tid & 15) << 2;

    const float* __restrict__ A = CGATE ? g_Au : g_Ah;
    const float* ag = A + (size_t)(r0 + lrow)*HH + lk4;
    const float* bg = Wh + (size_t)bk*G3 + (CGATE ? 512 : 0) + j0 + bc4;

    u64 acc[2][4];
    #pragma unroll
    for (int i=0;i<2;i++){ acc[i][0]=0; acc[i][1]=0; acc[i][2]=0; acc[i][3]=0; }

    float4 a0 = __ldcg((const float4*)ag);
    float4 b0 = __ldg((const float4*)bg);

    for (int kc = 0; kc < 256; kc += 16){
        sA[(lk4+0)*68 + lrow] = a0.x;
        sA[(lk4+1)*68 + lrow] = a0.y;
        sA[(lk4+2)*68 + lrow] = a0.z;
        sA[(lk4+3)*68 + lrow] = a0.w;
        *(float4*)(sB + bk*132 + bc4)      = make_float4(b0.x, b0.x, b0.y, b0.y);
        *(float4*)(sB + bk*132 + 64 + bc4) = make_float4(b0.z, b0.z, b0.w, b0.w);
        __syncthreads();
        if (kc + 16 < 256){
            a0 = __ldcg((const float4*)(ag + kc + 16));
            b0 = __ldg((const float4*)(bg + (size_t)(kc + 16)*G3));
        }
        #pragma unroll
        for (int p = 0; p < 16; p++){
            F4U av, bu0, bu1;
            av.f  = *(const float4*)(sA + p*68 + (ty << 2));
            bu0.f = *(const float4*)(sB + p*132 + (tx << 2));
            bu1.f = *(const float4*)(sB + p*132 + 64 + (tx << 2));
            u64 ap[2] = { av.u[0], av.u[1] };
            u64 bd[4] = { bu0.u[0], bu0.u[1], bu1.u[0], bu1.u[1] };
            #pragma unroll
            for (int i = 0; i < 2; i++){
                ffma2(acc[i][0], ap[i], bd[0]);
                ffma2(acc[i][1], ap[i], bd[1]);
                ffma2(acc[i][2], ap[i], bd[2]);
                ffma2(acc[i][3], ap[i], bd[3]);
            }
        }
        __syncthreads();
    }

    // epilogue (R1 semantics)
    #pragma unroll
    for (int i = 0; i < 2; i++){
        #pragma unroll
        for (int j = 0; j < 4; j++){
            float2 v2 = unpack2(acc[i][j]);
            #pragma unroll
            for (int rr = 0; rr < 2; rr++){
                int row = r0 + (ty << 2) + 2*i + rr;
                float val = rr ? v2.y : v2.x;
                int b = row >> 8, n = row & 255;
                int jc = j0 + (tx << 2) + j;
                size_t gxbase = (((size_t)(b*TT + t))*NN + n)*G3;
                if (CGATE == 0){
                    float g = g_gx[gxbase + jc];
                    float s = sigmoidf_(val + g);
                    if (j0 < 256){
                        g_z[(size_t)row*HH + jc] = s;
                    } else {
                        int j2 = jc - 256;
                        g_u[(size_t)row*HH + j2] = s * g_h[(size_t)row*HH + j2];
                    }
                } else {
                    float g = g_gx[gxbase + 512 + jc];
                    float c = tanhf(val + g);
                    size_t idx = (size_t)row*HH + jc;
                    float zv = g_z[idx];
                    float hn = zv * g_h[idx] + (1.0f - zv) * c;
                    g_h[idx] = hn;
                    g_hseq[(((size_t)(b*TT + t))*NN + n)*HH + jc] = hn;
                }
            }
        }
    }
}

// ---------------- sequence sparse conv (R1-proven): g_Axseq = A (x) g_hseq ----------------
__global__ void spconv_seq(){
    __shared__ float Xs[NN*32];
    int kh = blockIdx.x;       // 0..7
    int q  = blockIdx.y;       // 0..511
    int tid = threadIdx.x;
    const float4* X4 = (const float4*)g_hseq;
    float4* Xs4 = (float4*)Xs;
    for (int i = tid; i < NN*8; i += 256){
        int m = i >> 3, c4 = i & 7;
        Xs4[i] = X4[((size_t)q*NN + m)*64 + kh*8 + c4];
    }
    __syncthreads();
    int k  = tid & 31;
    int ng = tid >> 5;         // 0..7
    for (int nb = 0; nb < NN; nb += 8){
        int n = nb + ng;
        int cn = g_cnt[n];
        const int*   cp = g_col + n*NN;
        const float* vp = g_val + n*NN;
        float a0 = 0.0f, a1 = 0.0f;
        int e = 0;
        for (; e + 2 <= cn; e += 2){
            a0 += vp[e]   * Xs[(cp[e]   << 5) + k];
            a1 += vp[e+1] * Xs[(cp[e+1] << 5) + k];
        }
        if (e < cn) a0 += vp[e] * Xs[(cp[e] << 5) + k];
        g_Axseq[((size_t)q*NN + n)*HH + (kh << 5) + k] = a0 + a1;
    }
}

// ---------------- R1-proven 64x64x16 fp32 GEMM body (used by gemm_gx1 only) ----------------
#define GEMM64x64(ABASE, ALd, BBASE, BLd)                                           \
    do {                                                                            \
        for (int kk = 0; kk < HH; kk += 16){                                        \
            float4 av = *(const float4*)((ABASE) + (size_t)(r0+li)*(ALd) + kk + lp4); \
            As[lp4+0][li]=av.x; As[lp4+1][li]=av.y; As[lp4+2][li]=av.z; As[lp4+3][li]=av.w; \
            float4 bv = *(const float4*)((BBASE) + (size_t)(kk+bp)*(BLd) + bj4);    \
            *(float4*)&Bs[bp][bj4] = bv;                                            \
            __syncthreads();                                                        \
            _Pragma("unroll")                                                       \
            for (int p = 0; p < 16; p++){                                           \
                float4 a = *(const float4*)&As[p][ty*4];                            \
                float4 b = *(const float4*)&Bs[p][tx*4];                            \
                acc[0][0]+=a.x*b.x; acc[0][1]+=a.x*b.y; acc[0][2]+=a.x*b.z; acc[0][3]+=a.x*b.w; \
                acc[1][0]+=a.y*b.x; acc[1][1]+=a.y*b.y; acc[1][2]+=a.y*b.z; acc[1][3]+=a.y*b.w; \
                acc[2][0]+=a.z*b.x; acc[2][1]+=a.z*b.y; acc[2][2]+=a.z*b.z; acc[2][3]+=a.z*b.w; \
                acc[3][0]+=a.w*b.x; acc[3][1]+=a.w*b.y; acc[3][2]+=a.w*b.z; acc[3][3]+=a.w*b.w; \
            }                                                                       \
            __syncthreads();                                                        \
        }                                                                           \
    } while(0)

#define GEMM_PROLOGUE                          \
    __shared__ float As[16][64];               \
    __shared__ float Bs[16][64];               \
    int tid = threadIdx.x;                     \
    int r0 = blockIdx.y * 64;                  \
    int j0 = blockIdx.x * 64;                  \
    int ty = tid >> 4, tx = tid & 15;          \
    int li = tid >> 2;                         \
    int lp4 = (tid & 3) * 4;                   \
    int bp = tid >> 4;                         \
    int bj4 = (tid & 15) * 4;                  \
    float acc[4][4] = {};

// layer-1 gx: g_gx = g_Axseq @ Wx1 + b1   ([131072,256] x [256,768]) — R1-proven scalar
__global__ void gemm_gx1(const float* __restrict__ Wx1, const float* __restrict__ b1){
    GEMM_PROLOGUE
    GEMM64x64(g_Axseq, HH, Wx1 + j0, G3);
    #pragma unroll
    for (int ii = 0; ii < 4; ii++)
    #pragma unroll
    for (int jj = 0; jj < 4; jj++){
        int r = r0 + ty*4 + ii;
        int j = j0 + tx*4 + jj;
        g_gx[(size_t)r*G3 + j] = acc[ii][jj] + b1[j];
    }
}

// ---------------- output head (R1-proven) ----------------
__global__ void out_head(const float* __restrict__ Wout, const float* __restrict__ bout,
                         float* __restrict__ out){
    __shared__ float sh[32*257];
    __shared__ float Ws[HH*DO];
    __shared__ float bs[DO];
    int r0 = blockIdx.x * 32;
    int tid = threadIdx.x;
    for (int i = tid; i < HH*DO; i += 256) Ws[i] = Wout[i];
    if (tid < DO) bs[tid] = bout[tid];
    const float4* H4 = (const float4*)g_hseq;
    for (int i = tid; i < 32*64; i += 256){
        int rr = i >> 6, c4 = i & 63;
        float4 v = H4[((size_t)(r0 + rr))*64 + c4];
        float* dst = &sh[rr*257 + c4*4];
        dst[0]=v.x; dst[1]=v.y; dst[2]=v.z; dst[3]=v.w;
    }
    __syncthreads();
    for (int oi = tid; oi < 32*DO; oi += 256){
        int rr = oi / DO, c = oi % DO;
        float a0 = bs[c], a1 = 0.0f;
        const float* sr = &sh[rr*257];
        for (int k = 0; k < HH; k += 2){
            a0 += sr[k]   * Ws[k*DO + c];
            a1 += sr[k+1] * Ws[(k+1)*DO + c];
        }
        out[(size_t)(r0 + rr)*DO + c] = a0 + a1;
    }
}

// ---------------- launch (R1 orchestration; gate GEMMs -> f32x2) ----------------
extern "C" void kernel_launch(void* const* d_in, const int* in_sizes, int n_in,
                              void* d_out, int out_size) {
    const float* x2d  = (const float*)d_in[0];
    const float* mask = (const float*)d_in[1];
    const float* adj  = (const float*)d_in[2];
    const float* Wx0  = (const float*)d_in[3];
    const float* Wh0  = (const float*)d_in[4];
    const float* b0   = (const float*)d_in[5];
    const float* Wx1  = (const float*)d_in[6];
    const float* Wh1  = (const float*)d_in[7];
    const float* b1   = (const float*)d_in[8];
    const float* Wout = (const float*)d_in[9];
    const float* bout = (const float*)d_in[10];
    float* out = (float*)d_out;

    build_csr<<<1, 256>>>(adj);
    prep_gx0<<<BB*TT, 256>>>(x2d, mask, Wx0, b0);

    // ---- layer 0 recurrence ----
    zero_h<<<2048, 256>>>();
    for (int t = 0; t < TT; t++){
        spconv_step<<<BB*NN, 256>>>(0);
        gemm_gate<0><<<dim3(8, 32), 256>>>(Wh0, t);
        spconv_step<<<BB*NN, 256>>>(1);
        gemm_gate<1><<<dim3(4, 32), 256>>>(Wh0, t);
    }

    // ---- layer 1 gx precompute (parallel over all t) ----
    spconv_seq<<<dim3(8, BB*TT), 256>>>();
    gemm_gx1<<<dim3(12, (BB*TT*NN)/64), 256>>>(Wx1, b1);

    // ---- layer 1 recurrence ----
    zero_h<<<2048, 256>>>();
    for (int t = 0; t < TT; t++){
        spconv_step<<<BB*NN, 256>>>(0);
        gemm_gate<0><<<dim3(8, 32), 256>>>(Wh1, t);
        spconv_step<<<BB*NN, 256>>>(1);
        gemm_gate<1><<<dim3(4, 32), 256>>>(Wh1, t);
    }

    // ---- output head ----
    out_head<<<(BB*TT*NN)/32, 256>>>(Wout, bout, out);
}

// round 11
// speedup vs baseline: 1.6370x; 1.1718x over previous
#include <cuda_runtime.h>
#include <math.h>

#define BB 8
#define TT 64
#define NN 256
#define HH 256
#define DI 6
#define DO 9
#define G3 (3*HH)   // 768

// ---------------- scratch (device globals; no runtime allocation) ----------------
__device__ __align__(16) float g_gx[(size_t)BB*TT*NN*G3];
__device__ __align__(16) float g_hseq[(size_t)BB*TT*NN*HH];
__device__ __align__(16) float g_Axseq[(size_t)BB*TT*NN*HH];
__device__ __align__(16) float g_h [BB*NN*HH];
__device__ __align__(16) float g_Ah[BB*NN*HH];
__device__ __align__(16) float g_z [BB*NN*HH];
__device__ __align__(16) float g_u [BB*NN*HH];
__device__ __align__(16) float g_Au[BB*NN*HH];
__device__ int   g_cnt[NN];
__device__ int   g_col[NN*NN];
__device__ float g_val[NN*NN];

__device__ __forceinline__ float sigmoidf_(float x){ return 1.0f / (1.0f + expf(-x)); }

// ---------------- CSR build from dense adjacency (zeros are exact) ----------------
__global__ void build_csr(const float* __restrict__ adj){
    int n = threadIdx.x;
    int c = 0;
    for (int m = 0; m < NN; m++){
        float v = adj[n*NN + m];
        if (v != 0.0f){ g_col[n*NN + c] = m; g_val[n*NN + c] = v; c++; }
    }
    g_cnt[n] = c;
}

__global__ void zero_h(){
    int i = blockIdx.x * 256 + threadIdx.x;
    g_h[i] = 0.0f;
}

// ---------------- layer-0 gx: per (b,t), gx = (A (x) (x*mask)) @ Wx0 + b0 ----------------
__global__ void prep_gx0(const float* __restrict__ x2d, const float* __restrict__ mask,
                         const float* __restrict__ Wx0, const float* __restrict__ b0){
    __shared__ float xm[NN*DI];
    __shared__ float ax[NN*DI];
    __shared__ float Ws[DI*G3];
    int bt = blockIdx.x;
    int tid = threadIdx.x;

    for (int i = tid; i < NN*DI; i += 256){
        int n = i / DI;
        xm[i] = x2d[(size_t)bt*NN*DI + i] * mask[(size_t)bt*NN + n];
    }
    for (int i = tid; i < DI*G3; i += 256) Ws[i] = Wx0[i];
    __syncthreads();

    {   // sparse conv: one node per thread
        int n = tid;
        float a0=0,a1=0,a2=0,a3=0,a4=0,a5=0;
        int cn = g_cnt[n];
        for (int e = 0; e < cn; e++){
            int m = g_col[n*NN + e];
            float w = g_val[n*NN + e];
            const float* xr = xm + m*DI;
            a0 += w*xr[0]; a1 += w*xr[1]; a2 += w*xr[2];
            a3 += w*xr[3]; a4 += w*xr[4]; a5 += w*xr[5];
        }
        float* ar = ax + n*DI;
        ar[0]=a0; ar[1]=a1; ar[2]=a2; ar[3]=a3; ar[4]=a4; ar[5]=a5;
    }
    __syncthreads();

    for (int jj = 0; jj < 3; jj++){
        int j = tid + (jj << 8);
        float w0=Ws[j], w1=Ws[G3+j], w2=Ws[2*G3+j], w3=Ws[3*G3+j], w4=Ws[4*G3+j], w5=Ws[5*G3+j];
        float bj = b0[j];
        float* gout = g_gx + (size_t)bt*NN*G3 + j;
        for (int n = 0; n < NN; n++){
            const float* axr = ax + n*DI;
            float s = bj + axr[0]*w0 + axr[1]*w1 + axr[2]*w2
                         + axr[3]*w3 + axr[4]*w4 + axr[5]*w5;
            gout[(size_t)n*G3] = s;
        }
    }
}

// ---------------- per-step sparse conv, float4-vectorized ----------------
// block = 64 threads (each owns 4 k-cols); grid = (q,n) = 2048.
// 4-deep unroll -> 4 independent float4 accumulators (MLP 4 vs L2 latency).
__global__ void __launch_bounds__(64,16) spconv_step(int which){
    const float* __restrict__ X = which ? g_u  : g_h;
    float* __restrict__       C = which ? g_Au : g_Ah;
    int n = blockIdx.x & 255;
    int q = blockIdx.x >> 8;
    int k4 = threadIdx.x;     // float4 lane: cols [k4*4, k4*4+4)
    int cn = g_cnt[n];
    const int*   cp = g_col + n*NN;
    const float* vp = g_val + n*NN;
    const float4* Xb = (const float4*)(X + (size_t)q*NN*HH) + k4;
    float4 a0 = make_float4(0,0,0,0), a1 = a0, a2 = a0, a3 = a0;
    int e = 0;
    for (; e + 4 <= cn; e += 4){
        float w0 = vp[e],   w1 = vp[e+1], w2 = vp[e+2], w3 = vp[e+3];
        float4 x0 = Xb[(size_t)cp[e]   << 6];
        float4 x1 = Xb[(size_t)cp[e+1] << 6];
        float4 x2 = Xb[(size_t)cp[e+2] << 6];
        float4 x3 = Xb[(size_t)cp[e+3] << 6];
        a0.x += w0*x0.x; a0.y += w0*x0.y; a0.z += w0*x0.z; a0.w += w0*x0.w;
        a1.x += w1*x1.x; a1.y += w1*x1.y; a1.z += w1*x1.z; a1.w += w1*x1.w;
        a2.x += w2*x2.x; a2.y += w2*x2.y; a2.z += w2*x2.z; a2.w += w2*x2.w;
        a3.x += w3*x3.x; a3.y += w3*x3.y; a3.z += w3*x3.z; a3.w += w3*x3.w;
    }
    for (; e < cn; e++){
        float w = vp[e];
        float4 x = Xb[(size_t)cp[e] << 6];
        a0.x += w*x.x; a0.y += w*x.y; a0.z += w*x.z; a0.w += w*x.w;
    }
    float4 r;
    r.x = (a0.x + a1.x) + (a2.x + a3.x);
    r.y = (a0.y + a1.y) + (a2.y + a3.y);
    r.z = (a0.z + a1.z) + (a2.z + a3.z);
    r.w = (a0.w + a1.w) + (a2.w + a3.w);
    ((float4*)(C + (size_t)q*NN*HH + (n << 8)))[k4] = r;
}

// ---------------- sequence sparse conv (R1-proven): g_Axseq = A (x) g_hseq ----------------
__global__ void spconv_seq(){
    __shared__ float Xs[NN*32];
    int kh = blockIdx.x;       // 0..7
    int q  = blockIdx.y;       // 0..511
    int tid = threadIdx.x;
    const float4* X4 = (const float4*)g_hseq;
    float4* Xs4 = (float4*)Xs;
    for (int i = tid; i < NN*8; i += 256){
        int m = i >> 3, c4 = i & 7;
        Xs4[i] = X4[((size_t)q*NN + m)*64 + kh*8 + c4];
    }
    __syncthreads();
    int k  = tid & 31;
    int ng = tid >> 5;         // 0..7
    for (int nb = 0; nb < NN; nb += 8){
        int n = nb + ng;
        int cn = g_cnt[n];
        const int*   cp = g_col + n*NN;
        const float* vp = g_val + n*NN;
        float a0 = 0.0f, a1 = 0.0f;
        int e = 0;
        for (; e + 2 <= cn; e += 2){
            a0 += vp[e]   * Xs[(cp[e]   << 5) + k];
            a1 += vp[e+1] * Xs[(cp[e+1] << 5) + k];
        }
        if (e < cn) a0 += vp[e] * Xs[(cp[e] << 5) + k];
        g_Axseq[((size_t)q*NN + n)*HH + (kh << 5) + k] = a0 + a1;
    }
}

// ---------------- R1-proven 64x64x16 fp32 GEMM body ----------------
#define GEMM64x64(ABASE, ALd, BBASE, BLd)                                           \
    do {                                                                            \
        for (int kk = 0; kk < HH; kk += 16){                                        \
            float4 av = *(const float4*)((ABASE) + (size_t)(r0+li)*(ALd) + kk + lp4); \
            As[lp4+0][li]=av.x; As[lp4+1][li]=av.y; As[lp4+2][li]=av.z; As[lp4+3][li]=av.w; \
            float4 bv = *(const float4*)((BBASE) + (size_t)(kk+bp)*(BLd) + bj4);    \
            *(float4*)&Bs[bp][bj4] = bv;                                            \
            __syncthreads();                                                        \
            _Pragma("unroll")                                                       \
            for (int p = 0; p < 16; p++){                                           \
                float4 a = *(const float4*)&As[p][ty*4];                            \
                float4 b = *(const float4*)&Bs[p][tx*4];                            \
                acc[0][0]+=a.x*b.x; acc[0][1]+=a.x*b.y; acc[0][2]+=a.x*b.z; acc[0][3]+=a.x*b.w; \
                acc[1][0]+=a.y*b.x; acc[1][1]+=a.y*b.y; acc[1][2]+=a.y*b.z; acc[1][3]+=a.y*b.w; \
                acc[2][0]+=a.z*b.x; acc[2][1]+=a.z*b.y; acc[2][2]+=a.z*b.z; acc[2][3]+=a.z*b.w; \
                acc[3][0]+=a.w*b.x; acc[3][1]+=a.w*b.y; acc[3][2]+=a.w*b.z; acc[3][3]+=a.w*b.w; \
            }                                                                       \
            __syncthreads();                                                        \
        }                                                                           \
    } while(0)

#define GEMM_PROLOGUE                          \
    __shared__ float As[16][64];               \
    __shared__ float Bs[16][64];               \
    int tid = threadIdx.x;                     \
    int r0 = blockIdx.y * 64;                  \
    int j0 = blockIdx.x * 64;                  \
    int ty = tid >> 4, tx = tid & 15;          \
    int li = tid >> 2;                         \
    int lp4 = (tid & 3) * 4;                   \
    int bp = tid >> 4;                         \
    int bj4 = (tid & 15) * 4;                  \
    float acc[4][4] = {};

// z/r gates: gzr = Ah @ Wh[:, :512] + gx[:, :512]; z=sig, r=sig, u=r*h
__global__ void gemm_zr(const float* __restrict__ Wh, int t){
    GEMM_PROLOGUE
    GEMM64x64(g_Ah, HH, Wh + j0, G3);
    #pragma unroll
    for (int ii = 0; ii < 4; ii++)
    #pragma unroll
    for (int jj = 0; jj < 4; jj++){
        int r = r0 + ty*4 + ii;
        int j = j0 + tx*4 + jj;
        int b = r >> 8, n = r & 255;
        float val = acc[ii][jj] + g_gx[(((size_t)(b*TT + t))*NN + n)*G3 + j];
        if (j < HH){
            g_z[(size_t)r*HH + j] = sigmoidf_(val);
        } else {
            int j2 = j - HH;
            float rr = sigmoidf_(val);
            g_u[(size_t)r*HH + j2] = rr * g_h[(size_t)r*HH + j2];
        }
    }
}

// c gate + state update: c = tanh(Au @ Wh[:,512:] + gx[:,512:]); h = z*h + (1-z)*c
__global__ void gemm_c(const float* __restrict__ Wh, int t){
    GEMM_PROLOGUE
    GEMM64x64(g_Au, HH, Wh + 512 + j0, G3);
    #pragma unroll
    for (int ii = 0; ii < 4; ii++)
    #pragma unroll
    for (int jj = 0; jj < 4; jj++){
        int r = r0 + ty*4 + ii;
        int j = j0 + tx*4 + jj;
        int b = r >> 8, n = r & 255;
        float val = acc[ii][jj] + g_gx[(((size_t)(b*TT + t))*NN + n)*G3 + 512 + j];
        float c = tanhf(val);
        size_t idx = (size_t)r*HH + j;
        float zv = g_z[idx];
        float hn = zv * g_h[idx] + (1.0f - zv) * c;
        g_h[idx] = hn;
        g_hseq[(((size_t)(b*TT + t))*NN + n)*HH + j] = hn;
    }
}

// layer-1 gx: g_gx = g_Axseq @ Wx1 + b1   ([131072,256] x [256,768])
__global__ void gemm_gx1(const float* __restrict__ Wx1, const float* __restrict__ b1){
    GEMM_PROLOGUE
    GEMM64x64(g_Axseq, HH, Wx1 + j0, G3);
    #pragma unroll
    for (int ii = 0; ii < 4; ii++)
    #pragma unroll
    for (int jj = 0; jj < 4; jj++){
        int r = r0 + ty*4 + ii;
        int j = j0 + tx*4 + jj;
        g_gx[(size_t)r*G3 + j] = acc[ii][jj] + b1[j];
    }
}

// ---------------- output head (R1-proven) ----------------
__global__ void out_head(const float* __restrict__ Wout, const float* __restrict__ bout,
                         float* __restrict__ out){
    __shared__ float sh[32*257];
    __shared__ float Ws[HH*DO];
    __shared__ float bs[DO];
    int r0 = blockIdx.x * 32;
    int tid = threadIdx.x;
    for (int i = tid; i < HH*DO; i += 256) Ws[i] = Wout[i];
    if (tid < DO) bs[tid] = bout[tid];
    const float4* H4 = (const float4*)g_hseq;
    for (int i = tid; i < 32*64; i += 256){
        int rr = i >> 6, c4 = i & 63;
        float4 v = H4[((size_t)(r0 + rr))*64 + c4];
        float* dst = &sh[rr*257 + c4*4];
        dst[0]=v.x; dst[1]=v.y; dst[2]=v.z; dst[3]=v.w;
    }
    __syncthreads();
    for (int oi = tid; oi < 32*DO; oi += 256){
        int rr = oi / DO, c = oi % DO;
        float a0 = bs[c], a1 = 0.0f;
        const float* sr = &sh[rr*257];
        for (int k = 0; k < HH; k += 2){
            a0 += sr[k]   * Ws[k*DO + c];
            a1 += sr[k+1] * Ws[(k+1)*DO + c];
        }
        out[(size_t)(r0 + rr)*DO + c] = a0 + a1;
    }
}

// ---------------- launch (R1 orchestration; spconv vectorized) ----------------
extern "C" void kernel_launch(void* const* d_in, const int* in_sizes, int n_in,
                              void* d_out, int out_size) {
    const float* x2d  = (const float*)d_in[0];
    const float* mask = (const float*)d_in[1];
    const float* adj  = (const float*)d_in[2];
    const float* Wx0  = (const float*)d_in[3];
    const float* Wh0  = (const float*)d_in[4];
    const float* b0   = (const float*)d_in[5];
    const float* Wx1  = (const float*)d_in[6];
    const float* Wh1  = (const float*)d_in[7];
    const float* b1   = (const float*)d_in[8];
    const float* Wout = (const float*)d_in[9];
    const float* bout = (const float*)d_in[10];
    float* out = (float*)d_out;

    build_csr<<<1, 256>>>(adj);
    prep_gx0<<<BB*TT, 256>>>(x2d, mask, Wx0, b0);

    // ---- layer 0 recurrence ----
    zero_h<<<2048, 256>>>();
    for (int t = 0; t < TT; t++){
        spconv_step<<<BB*NN, 64>>>(0);
        gemm_zr<<<dim3(8, (BB*NN)/64), 256>>>(Wh0, t);
        spconv_step<<<BB*NN, 64>>>(1);
        gemm_c<<<dim3(4, (BB*NN)/64), 256>>>(Wh0, t);
    }

    // ---- layer 1 gx precompute (parallel over all t) ----
    spconv_seq<<<dim3(8, BB*TT), 256>>>();
    gemm_gx1<<<dim3(12, (BB*TT*NN)/64), 256>>>(Wx1, b1);

    // ---- layer 1 recurrence ----
    zero_h<<<2048, 256>>>();
    for (int t = 0; t < TT; t++){
        spconv_step<<<BB*NN, 64>>>(0);
        gemm_zr<<<dim3(8, (BB*NN)/64), 256>>>(Wh1, t);
        spconv_step<<<BB*NN, 64>>>(1);
        gemm_c<<<dim3(4, (BB*NN)/64), 256>>>(Wh1, t);
    }

    // ---- output head ----
    out_head<<<(BB*TT*NN)/32, 256>>>(Wout, bout, out);
}